// round 7
// baseline (speedup 1.0000x reference)
#include <cuda_runtime.h>
#include <cuda_bf16.h>
#include <cstdint>
#include <math.h>

#define NROWS 16384
#define NHALF 8192
#define DDIM  256
#define NT    128          // 128-col j tiles
#define NMB   64           // 256-row M blocks
#define SEGW  8
#define NSEG  544          // sum_m ceil((128-2m)/8)
#define GT    256
#define GRID_P 152

// ---- device scratch ----
__device__ __nv_bfloat16 g_zn[NROWS * DDIM];
__device__ float  g_pos[NROWS];
__device__ float  g_S[NROWS];
__device__ double g_part[64];
__device__ int    g_ticket;
__device__ int    g_done = 0;

// ---- gemm smem: A 128KB (256 rows), B 64KB (128 j-rows), ticket ----
#define OFF_A    0
#define OFF_B    131072
#define OFF_BC   196608
#define SMEM_TOTAL 196624

#define C1F 14.42695040888963f   // 10*log2(e)

// ============================ helpers ============================
__device__ __forceinline__ uint32_t smem_u32(const void* p) {
    uint32_t a;
    asm("{ .reg .u64 t; cvta.to.shared.u64 t, %1; cvt.u32.u64 %0, t; }"
        : "=r"(a) : "l"(p));
    return a;
}
__device__ __forceinline__ void ldsm_x4(uint32_t& r0, uint32_t& r1,
                                        uint32_t& r2, uint32_t& r3,
                                        uint32_t addr) {
    asm volatile("ldmatrix.sync.aligned.m8n8.x4.shared.b16 {%0,%1,%2,%3}, [%4];"
                 : "=r"(r0), "=r"(r1), "=r"(r2), "=r"(r3) : "r"(addr));
}
__device__ __forceinline__ void mma16816(float* d, const uint32_t* a,
                                         uint32_t b0, uint32_t b1) {
    asm volatile(
        "mma.sync.aligned.m16n8k16.row.col.f32.bf16.bf16.f32 "
        "{%0,%1,%2,%3}, {%4,%5,%6,%7}, {%8,%9}, {%0,%1,%2,%3};"
        : "+f"(d[0]), "+f"(d[1]), "+f"(d[2]), "+f"(d[3])
        : "r"(a[0]), "r"(a[1]), "r"(a[2]), "r"(a[3]), "r"(b0), "r"(b1));
}
__device__ __forceinline__ float ex2f(float x) {
    float y; asm("ex2.approx.f32 %0, %1;" : "=f"(y) : "f"(x)); return y;
}
__device__ __forceinline__ void cp_commit() {
    asm volatile("cp.async.commit_group;" ::: "memory");
}
template <int N>
__device__ __forceinline__ void cp_wait() {
    asm volatile("cp.async.wait_group %0;" :: "n"(N) : "memory");
}
__device__ __forceinline__ void bar_quad(int id) {
    asm volatile("bar.sync %0, 128;" :: "r"(id) : "memory");
}
// A strip: 256 rows x 512B, full CTA (256 threads, 32 iters)
__device__ __forceinline__ void cp_tile_A(uint32_t sdst, int mblk, int tid) {
    const char* gp = reinterpret_cast<const char*>(g_zn) + (size_t)mblk * 131072;
    #pragma unroll
    for (int it = 0; it < 32; ++it) {
        int c = tid + it * GT;            // 0..8191 16B-chunks
        int r = c >> 5, cc = c & 31;
        uint32_t d = sdst + r * 512 + (((cc ^ (r & 7))) << 4);
        asm volatile("cp.async.cg.shared.global [%0], [%1], 16;"
                     :: "r"(d), "l"(gp + (size_t)c * 16) : "memory");
    }
}
// B slice: quad wn loads j-rows [wn*64, wn*64+64) of tile bj (128 threads, 16 iters)
__device__ __forceinline__ void cp_slice_B(uint32_t sbB, int bj, int wn,
                                           int quadtid) {
    const char* gp = reinterpret_cast<const char*>(g_zn)
                     + ((size_t)bj * 128 + wn * 64) * 512;
    #pragma unroll
    for (int it = 0; it < 16; ++it) {
        int c = quadtid + it * 128;       // 0..2047 16B-chunks
        int r = c >> 5, cc = c & 31;      // r 0..63
        uint32_t d = sbB + (wn * 64 + r) * 512 + (((cc ^ (r & 7))) << 4);
        asm volatile("cp.async.cg.shared.global [%0], [%1], 16;"
                     :: "r"(d), "l"(gp + (size_t)c * 16) : "memory");
    }
}

// ============================ K1: normalize + positives ============================
__global__ void norm_pos_kernel(const float* __restrict__ z1,
                                const float* __restrict__ z2) {
    int r = blockIdx.x;
    int t = threadIdx.x;          // 0..127
    int half = t >> 6, tt = t & 63;
    const float* src = (half ? z2 : z1) + (size_t)r * DDIM;
    float4 v = reinterpret_cast<const float4*>(src)[tt];
    float ss = v.x * v.x + v.y * v.y + v.z * v.z + v.w * v.w;
    #pragma unroll
    for (int o = 16; o; o >>= 1) ss += __shfl_xor_sync(0xffffffffu, ss, o);
    __shared__ float ws[4];
    __shared__ float sn[2][256];
    if ((t & 31) == 0) ws[t >> 5] = ss;
    __syncthreads();
    float inv = 1.0f / fmaxf(sqrtf(ws[half * 2] + ws[half * 2 + 1]), 1e-6f);
    float4 n;
    n.x = v.x * inv; n.y = v.y * inv; n.z = v.z * inv; n.w = v.w * inv;
    __nv_bfloat162 h0 = __floats2bfloat162_rn(n.x, n.y);
    __nv_bfloat162 h1 = __floats2bfloat162_rn(n.z, n.w);
    uint2 packed;
    packed.x = *reinterpret_cast<uint32_t*>(&h0);
    packed.y = *reinterpret_cast<uint32_t*>(&h1);
    int row = half ? r + NHALF : r;
    reinterpret_cast<uint2*>(g_zn + (size_t)row * DDIM)[tt] = packed;
    reinterpret_cast<float4*>(sn[half])[tt] = n;
    __syncthreads();
    float p = sn[0][t * 2] * sn[1][t * 2] + sn[0][t * 2 + 1] * sn[1][t * 2 + 1];
    #pragma unroll
    for (int o = 16; o; o >>= 1) p += __shfl_xor_sync(0xffffffffu, p, o);
    if ((t & 31) == 0) ws[t >> 5] = p;
    __syncthreads();
    if (t == 0) {
        float d = fminf(fmaxf(ws[0] + ws[1] + ws[2] + ws[3], -1.0f + 1e-6f),
                        1.0f - 1e-6f);
        g_pos[r] = d;
        g_pos[r + NHALF] = d;
        g_S[r] = 0.f;
        g_S[r + NHALF] = 0.f;
        if (r == 0) g_ticket = 0;
    }
}

// ===================== K2: persistent symmetric GEMM + LSE =====================
// CTA tile 256x128. warps: wn = wid>>2 (0..1, 64-col half), wm = wid&3 (0..3, 64-row).
// warp tile 64x64: acc[4 mf][8 nf][4 e]; e>>1 = row half (e2), e&1 = col bit (e1).
template <bool COLS>
__device__ __forceinline__ void epilogue(float (&acc)[4][8][4],
                                         float (&rsum)[4][2],
                                         int colbase,   // bj*128 + wn*64
                                         int lane, bool m0, bool m1) {
    float csum[8][2];
    if (COLS) {
        #pragma unroll
        for (int nf = 0; nf < 8; ++nf) { csum[nf][0] = 0.f; csum[nf][1] = 0.f; }
    }
    #pragma unroll
    for (int mf = 0; mf < 4; ++mf)
        #pragma unroll
        for (int nf = 0; nf < 8; ++nf)
            #pragma unroll
            for (int e = 0; e < 4; ++e) {
                float ev = ex2f(fmaf(acc[mf][nf][e], C1F, -C1F));
                // diag: col nf*8+q*2+e1 == row mf*16+(e>>1)*8+g  <=>
                // nf == 2*mf+(e>>1)  (compile-time)  &&  g == q*2+(e&1) (m0/m1)
                if (nf == 2 * mf + (e >> 1)) {
                    if ((e & 1) ? m1 : m0) ev = 0.f;
                }
                rsum[mf][e >> 1] += ev;
                if (COLS) csum[nf][e & 1] += ev;
                acc[mf][nf][e] = 0.f;
            }
    if (COLS) {
        const int q = lane & 3;
        #pragma unroll
        for (int nf = 0; nf < 8; ++nf)
            #pragma unroll
            for (int e1 = 0; e1 < 2; ++e1) {
                float v = csum[nf][e1];
                v += __shfl_xor_sync(0xffffffffu, v, 4);
                v += __shfl_xor_sync(0xffffffffu, v, 8);
                v += __shfl_xor_sync(0xffffffffu, v, 16);
                if (lane < 4)
                    atomicAdd(&g_S[colbase + nf * 8 + q * 2 + e1], v);
            }
    }
}

__device__ __forceinline__ void flush_rsum(float (&rsum)[4][2], int mblk,
                                           int wm, int lane) {
    const int g = lane >> 2, q = lane & 3;
    #pragma unroll
    for (int mf = 0; mf < 4; ++mf)
        #pragma unroll
        for (int h = 0; h < 2; ++h) {
            float v = rsum[mf][h];
            v += __shfl_xor_sync(0xffffffffu, v, 1);
            v += __shfl_xor_sync(0xffffffffu, v, 2);
            if (q == 0)
                atomicAdd(&g_S[mblk * 256 + wm * 64 + mf * 16 + h * 8 + g], v);
            rsum[mf][h] = 0.f;
        }
}

__global__ void __launch_bounds__(GT, 1) gemm_sym_kernel() {
    extern __shared__ char smem[];
    const int tid = threadIdx.x, lane = tid & 31, wid = tid >> 5;
    const int wn = wid >> 2, wm = wid & 3;
    const int quadtid = wm * 32 + lane;
    const int g = lane >> 2, q = lane & 3;
    uint32_t sb = smem_u32(smem);
    int* sBC = reinterpret_cast<int*>(smem + OFF_BC);

    // fragment addressing (proven scheme)
    const int aRow = lane & 15;
    const int aSel = lane >> 4;
    const int bRowOff = (lane & 7) + ((lane >> 4) << 3);
    const int bSel = (lane >> 3) & 1;
    const int aR7 = aRow & 7, bR7 = bRowOff & 7;
    uint32_t aB[4], bB[4];
    #pragma unroll
    for (int mf = 0; mf < 4; ++mf)
        aB[mf] = sb + OFF_A + (wm * 64 + mf * 16 + aRow) * 512;
    #pragma unroll
    for (int p = 0; p < 4; ++p)
        bB[p] = sb + OFF_B + (wn * 64 + p * 16 + bRowOff) * 512;

    // diag mask lane qualifiers (when this warp sits on a diagonal 64x64 block)
    const bool dwarp = (wn == (wm & 1));
    const bool dm0 = dwarp && (g == q * 2);
    const bool dm1 = dwarp && (g == q * 2 + 1);

    float acc[4][8][4];
    #pragma unroll
    for (int mf = 0; mf < 4; ++mf)
        #pragma unroll
        for (int nf = 0; nf < 8; ++nf)
            #pragma unroll
            for (int e = 0; e < 4; ++e) acc[mf][nf][e] = 0.f;
    float rsum[4][2];
    #pragma unroll
    for (int mf = 0; mf < 4; ++mf) { rsum[mf][0] = 0.f; rsum[mf][1] = 0.f; }

    const int barid = 1 + wn;
    int cur_m = -1;

    for (;;) {
        if (tid == 0) sBC[0] = atomicAdd(&g_ticket, 1);
        __syncthreads();
        int c = sBC[0];
        if (c >= NSEG) break;

        // decode segment -> (m, j0, len)
        int idx = c, m = 0;
        for (;;) {
            int ns = (NT - 2 * m + SEGW - 1) >> 3;
            if (idx < ns) break;
            idx -= ns; ++m;
        }
        const int j0 = 2 * m + idx * SEGW;
        const int len = min(SEGW, NT - j0);

        if (m != cur_m) {
            if (cur_m >= 0) flush_rsum(rsum, cur_m, wm, lane);
            cp_tile_A(sb + OFF_A, m, tid);
            cur_m = m;
        }
        cp_slice_B(sb + OFF_B, j0, wn, quadtid);
        cp_commit();
        cp_wait<0>();
        __syncthreads();              // A + B(t0) visible CTA-wide

        for (int t = 0; t < len; ++t) {
            // ---- MMA over K = 256 ----
            #pragma unroll
            for (int kk = 0; kk < 16; ++kk) {
                uint32_t a[4][4], b[4][4];
                uint32_t aoff = (uint32_t)(((2 * kk + aSel) ^ aR7) << 4);
                #pragma unroll
                for (int mf = 0; mf < 4; ++mf)
                    ldsm_x4(a[mf][0], a[mf][1], a[mf][2], a[mf][3],
                            aB[mf] + aoff);
                uint32_t boff = (uint32_t)(((2 * kk + bSel) ^ bR7) << 4);
                #pragma unroll
                for (int p = 0; p < 4; ++p)
                    ldsm_x4(b[p][0], b[p][1], b[p][2], b[p][3],
                            bB[p] + boff);
                #pragma unroll
                for (int mf = 0; mf < 4; ++mf)
                    #pragma unroll
                    for (int nf = 0; nf < 8; ++nf)
                        mma16816(acc[mf][nf], a[mf],
                                 b[nf >> 1][(nf & 1) * 2],
                                 b[nf >> 1][(nf & 1) * 2 + 1]);
            }
            bar_quad(barid);          // quad done reading B(t)
            if (t + 1 < len) {
                cp_slice_B(sb + OFF_B, j0 + t + 1, wn, quadtid);
                cp_commit();
            }

            // ---- epilogue (overlaps B(t+1) cp latency) ----
            const int bj = j0 + t;
            const int jrel = bj - 2 * m;
            int mode;                 // 0 OFF, 1 DIAG(rows only), 2 SKIP
            if (jrel == 0)      mode = (wm < 2) ? 1 : 2;
            else if (jrel == 1) mode = (wm < 2) ? 0 : 1;
            else                mode = 0;

            if (mode == 0) {
                epilogue<true >(acc, rsum, bj * 128 + wn * 64, lane,
                                false, false);
            } else if (mode == 1) {
                epilogue<false>(acc, rsum, 0, lane, dm0, dm1);
            } else {
                #pragma unroll
                for (int mf = 0; mf < 4; ++mf)
                    #pragma unroll
                    for (int nf = 0; nf < 8; ++nf)
                        #pragma unroll
                        for (int e = 0; e < 4; ++e) acc[mf][nf][e] = 0.f;
            }

            if (t + 1 < len) {
                cp_wait<0>();
                bar_quad(barid);      // B(t+1) visible to quad
            }
        }
    }

    if (cur_m >= 0) flush_rsum(rsum, cur_m, wm, lane);
}

// ============================ K3: loss ============================
__global__ void loss_kernel(float* __restrict__ out) {
    int r = blockIdx.x * 256 + threadIdx.x;
    double v = (double)logf(g_S[r]) + 10.0 - 10.0 * (double)g_pos[r];
    #pragma unroll
    for (int o = 16; o; o >>= 1) v += __shfl_xor_sync(0xffffffffu, v, o);
    __shared__ double sd[8];
    if ((threadIdx.x & 31) == 0) sd[threadIdx.x >> 5] = v;
    __syncthreads();
    if (threadIdx.x == 0) {
        double a = 0.0;
        #pragma unroll
        for (int i = 0; i < 8; ++i) a += sd[i];
        g_part[blockIdx.x] = a;
        __threadfence();
        int n = atomicAdd(&g_done, 1);
        if (n == 63) {
            __threadfence();
            double s = 0.0;
            for (int i = 0; i < 64; ++i)
                s += *((volatile double*)&g_part[i]);
            out[0] = (float)(s / (double)NROWS);
            g_done = 0;
        }
    }
}

// ---------------------------------------------------------------------------
extern "C" void kernel_launch(void* const* d_in, const int* in_sizes, int n_in,
                              void* d_out, int out_size) {
    (void)in_sizes; (void)n_in; (void)out_size;
    const float* z1 = (const float*)d_in[0];
    const float* z2 = (const float*)d_in[1];
    float* out = (float*)d_out;

    cudaFuncSetAttribute(gemm_sym_kernel,
                         cudaFuncAttributeMaxDynamicSharedMemorySize, SMEM_TOTAL);

    norm_pos_kernel<<<NHALF, 128>>>(z1, z2);
    gemm_sym_kernel<<<GRID_P, GT, SMEM_TOTAL>>>();
    loss_kernel<<<64, 256>>>(out);
}